// round 12
// baseline (speedup 1.0000x reference)
#include <cuda_runtime.h>
#include <cuda_fp16.h>
#include <cstdint>

#define BATCH  8
#define SEQ    1024
#define DMODEL 1024
#define NHEAD  16
#define DK     64
#define DV     64
#define DOUT   1024
#define ATTN_OFF ((size_t)BATCH * SEQ * DOUT)

// ---------------------------------------------------------------------------
// f16 scratch
// ---------------------------------------------------------------------------
__device__ __align__(128) __half g_qh[(size_t)BATCH * SEQ * DMODEL];
__device__ __align__(128) __half g_kh[(size_t)BATCH * SEQ * DMODEL];
__device__ __align__(128) __half g_vh[(size_t)BATCH * SEQ * DMODEL];
__device__ __align__(128) __half g_Qh[(size_t)BATCH * NHEAD * SEQ * DK];  // [ba][n][d]
__device__ __align__(128) __half g_Kh[(size_t)BATCH * NHEAD * SEQ * DK];  // [ba][m][d]
__device__ __align__(128) __half g_Vh[(size_t)BATCH * NHEAD * SEQ * DV];  // [ba][m][j]
__device__ __align__(128) __half g_ktv[(size_t)BATCH * NHEAD * DK * DV];  // [ba][d][j]
__device__ __align__(128) __half g_neh[(size_t)BATCH * SEQ * NHEAD * DV]; // [b][n][a*64+j]
__device__ __align__(128) __half g_WqT[DMODEL * DMODEL];  // [out_col][in]
__device__ __align__(128) __half g_WkT[DMODEL * DMODEL];
__device__ __align__(128) __half g_WvT[DMODEL * DMODEL];
__device__ __align__(128) __half g_WoT[DMODEL * DMODEL];

// ---------------------------------------------------------------------------
// Helpers
// ---------------------------------------------------------------------------
__device__ __forceinline__ uint32_t smem_u32(const void* p) {
    return (uint32_t)__cvta_generic_to_shared(p);
}
__device__ __forceinline__ void cp16(uint32_t s, const void* g) {
    asm volatile("cp.async.cg.shared.global [%0], [%1], 16;" :: "r"(s), "l"(g));
}
__device__ __forceinline__ void cp_commit() {
    asm volatile("cp.async.commit_group;");
}
template<int N> __device__ __forceinline__ void cp_wait() {
    asm volatile("cp.async.wait_group %0;" :: "n"(N));
}
#define LDSM4(r0,r1,r2,r3,addr) \
    asm volatile("ldmatrix.sync.aligned.m8n8.x4.shared.b16 {%0,%1,%2,%3}, [%4];" \
        : "=r"(r0),"=r"(r1),"=r"(r2),"=r"(r3) : "r"(addr))
#define LDSM4T(r0,r1,r2,r3,addr) \
    asm volatile("ldmatrix.sync.aligned.m8n8.x4.trans.shared.b16 {%0,%1,%2,%3}, [%4];" \
        : "=r"(r0),"=r"(r1),"=r"(r2),"=r"(r3) : "r"(addr))
__device__ __forceinline__ void mma16816(float* c, const uint32_t* a,
                                         uint32_t b0, uint32_t b1) {
    asm volatile(
        "mma.sync.aligned.m16n8k16.row.col.f32.f16.f16.f32 "
        "{%0,%1,%2,%3}, {%4,%5,%6,%7}, {%8,%9}, {%0,%1,%2,%3};"
        : "+f"(c[0]), "+f"(c[1]), "+f"(c[2]), "+f"(c[3])
        : "r"(a[0]), "r"(a[1]), "r"(a[2]), "r"(a[3]), "r"(b0), "r"(b1));
}
__device__ __forceinline__ uint32_t packh2(float lo, float hi) {
    __half2 h = __floats2half2_rn(lo, hi);
    return *reinterpret_cast<uint32_t*>(&h);
}

// ---------------------------------------------------------------------------
// fp16 GEMM core: 128 threads, block 128x128, warp 64x64, BK=32,
// 3-stage cp.async ring (61.4KB smem -> co-residable with k_attn_s CTAs),
// one barrier per k-step.
// MODE 0: f16 head-scatter -> [ba][n][d]. MODE 4: f32 row-major ldc=1024.
// ---------------------------------------------------------------------------
template<int MODE>
__device__ __forceinline__ void hgemm(
    const __half* __restrict__ Ag, int lda,
    const __half* __restrict__ Bg, int ldb,
    int nkt, void* Cb, int mtile, int ntile, __half* smem)
{
    constexpr int LD = 40;
    constexpr int TS = 128 * LD;
    constexpr int STG = 2 * TS;

    const int tid = threadIdx.x, warp = tid >> 5, lane = tid & 31;
    const int wmb = (warp >> 1) * 64, wnb = (warp & 1) * 64;
    const int g = lane >> 2, tg = lane & 3;

    float acc[4][8][4];
    #pragma unroll
    for (int mi = 0; mi < 4; mi++)
        #pragma unroll
        for (int ni = 0; ni < 8; ni++)
            #pragma unroll
            for (int e = 0; e < 4; e++) acc[mi][ni][e] = 0.0f;

    auto issue = [&](int kt) {
        __half* S = smem + (kt % 3) * STG;
        #pragma unroll
        for (int it = 0; it < 4; it++) {
            int i = tid + it * 128;
            int row = i >> 2, c8 = (i & 3) * 8;
            cp16(smem_u32(S + row * LD + c8),
                 Ag + (size_t)(mtile * 128 + row) * lda + kt * 32 + c8);
        }
        #pragma unroll
        for (int it = 0; it < 4; it++) {
            int i = tid + it * 128;
            int row = i >> 2, c8 = (i & 3) * 8;
            cp16(smem_u32(S + TS + row * LD + c8),
                 Bg + (size_t)(ntile * 128 + row) * ldb + kt * 32 + c8);
        }
        cp_commit();
    };

    issue(0); issue(1);
    for (int kt = 0; kt < nkt; kt++) {
        if (kt == nkt - 1) cp_wait<0>(); else cp_wait<1>();
        __syncthreads();
        if (kt + 2 < nkt) issue(kt + 2);   // writes slot (kt-1)%3: safe post-barrier

        uint32_t smA = smem_u32(smem + (kt % 3) * STG);
        uint32_t smB = smA + TS * 2;

        #pragma unroll
        for (int ks = 0; ks < 2; ks++) {
            uint32_t a[4][4];
            #pragma unroll
            for (int mi = 0; mi < 4; mi++) {
                uint32_t ad = smA + (((wmb + mi * 16 + (lane & 15)) * LD)
                                     + ks * 16 + (lane >> 4) * 8) * 2;
                LDSM4(a[mi][0], a[mi][1], a[mi][2], a[mi][3], ad);
            }
            #pragma unroll
            for (int np = 0; np < 4; np++) {
                int n = wnb + np * 16 + (lane & 7) + ((lane >> 4) & 1) * 8;
                int koff = ks * 16 + ((lane >> 3) & 1) * 8;
                uint32_t b0, b1, b2, b3;
                LDSM4(b0, b1, b2, b3, smB + (n * LD + koff) * 2);
                #pragma unroll
                for (int mi = 0; mi < 4; mi++) {
                    mma16816(acc[mi][2 * np],     a[mi], b0, b1);
                    mma16816(acc[mi][2 * np + 1], a[mi], b2, b3);
                }
            }
        }
    }

    #pragma unroll
    for (int mi = 0; mi < 4; mi++) {
        #pragma unroll
        for (int ni = 0; ni < 8; ni++) {
            #pragma unroll
            for (int h = 0; h < 2; h++) {
                int r = mtile * 128 + wmb + mi * 16 + g + h * 8;
                int c = ntile * 128 + wnb + ni * 8 + 2 * tg;
                float v0 = acc[mi][ni][h * 2], v1 = acc[mi][ni][h * 2 + 1];
                if (MODE == 0) {
                    size_t idx = (size_t)((r >> 10) * NHEAD + (c >> 6)) * ((size_t)SEQ * 64)
                               + (size_t)(r & 1023) * 64 + (c & 63);
                    *reinterpret_cast<__half2*>((__half*)Cb + idx) = __floats2half2_rn(v0, v1);
                } else {
                    *reinterpret_cast<float2*>((float*)Cb + (size_t)r * 1024 + c)
                        = make_float2(v0, v1);
                }
            }
        }
    }
}

// ---------------------------------------------------------------------------
// Small kernels
// ---------------------------------------------------------------------------
__global__ void k_cvt(const float* __restrict__ q, const float* __restrict__ k,
                      const float* __restrict__ v) {
    int z = blockIdx.z;
    const float* src = (z == 0) ? q : (z == 1) ? k : v;
    __half* dst      = (z == 0) ? g_qh : (z == 1) ? g_kh : g_vh;
    size_t i = ((size_t)blockIdx.x * 256 + threadIdx.x) * 8;
    float4 a = *reinterpret_cast<const float4*>(src + i);
    float4 b = *reinterpret_cast<const float4*>(src + i + 4);
    __half2 h0 = __floats2half2_rn(a.x, a.y), h1 = __floats2half2_rn(a.z, a.w);
    __half2 h2 = __floats2half2_rn(b.x, b.y), h3 = __floats2half2_rn(b.z, b.w);
    uint4 o;
    o.x = *reinterpret_cast<uint32_t*>(&h0); o.y = *reinterpret_cast<uint32_t*>(&h1);
    o.z = *reinterpret_cast<uint32_t*>(&h2); o.w = *reinterpret_cast<uint32_t*>(&h3);
    *reinterpret_cast<uint4*>(dst + i) = o;
}

__global__ void k_transpose(const float* __restrict__ wq, const float* __restrict__ wk,
                            const float* __restrict__ wv, const float* __restrict__ wo) {
    __shared__ float t[32][33];
    int z = blockIdx.z;
    const float* in = (z == 0) ? wq : (z == 1) ? wk : (z == 2) ? wv : wo;
    __half* outp    = (z == 0) ? g_WqT : (z == 1) ? g_WkT : (z == 2) ? g_WvT : g_WoT;
    int xi = blockIdx.x * 32 + threadIdx.x;
    int yi = blockIdx.y * 32 + threadIdx.y;
    #pragma unroll
    for (int j = 0; j < 32; j += 8)
        t[threadIdx.y + j][threadIdx.x] = in[(size_t)(yi + j) * DMODEL + xi];
    __syncthreads();
    int xo = blockIdx.y * 32 + threadIdx.x;
    int yo = blockIdx.x * 32 + threadIdx.y;
    #pragma unroll
    for (int j = 0; j < 32; j += 8)
        outp[(size_t)(yo + j) * DMODEL + xo] = __float2half_rn(t[threadIdx.x][threadIdx.y + j]);
}

// zbase: 0 -> handles z = {0(Q), 1(K)}; 2 -> handles z = 2(V)
__global__ void __launch_bounds__(128, 2)
k_proj(int zbase) {
    extern __shared__ __half hsm[];
    int z = zbase + blockIdx.z;
    if (z == 0)
        hgemm<0>(g_qh, DMODEL, g_WqT, DMODEL, 32, g_Qh, blockIdx.x, blockIdx.y, hsm);
    else if (z == 1)
        hgemm<0>(g_kh, DMODEL, g_WkT, DMODEL, 32, g_Kh, blockIdx.x, blockIdx.y, hsm);
    else
        hgemm<0>(g_vh, DMODEL, g_WvT, DMODEL, 32, g_Vh, blockIdx.x, blockIdx.y, hsm);
}

__global__ void __launch_bounds__(128, 2)
k_out(float* __restrict__ out) {
    extern __shared__ __half hsm[];
    hgemm<4>(g_neh, NHEAD * DV, g_WoT, NHEAD * DV, 32, out, blockIdx.x, blockIdx.y, hsm);
}

// ---------------------------------------------------------------------------
// k_attn_s: S = Q K^T only — UNCHANGED (113.9us best).
// ---------------------------------------------------------------------------
#define QLD 72
#define KVLD 72
#define KTS (64 * KVLD)

__global__ void __launch_bounds__(256, 3)
k_attn_s(float* __restrict__ out) {
    extern __shared__ __half hsm[];
    __half* Qs = hsm;                    // [128][72]
    __half* Ks = hsm + 128 * QLD;        // [4 stages][64][72]

    const int tid = threadIdx.x, warp = tid >> 5, lane = tid & 31;
    const int g = lane >> 2, tg = lane & 3;
    const int mtile = blockIdx.x, ba = blockIdx.y;

    const __half* Kg = g_Kh + (size_t)ba * SEQ * DK;

    {
        const __half* Qg = g_Qh + ((size_t)ba * SEQ + mtile * 128) * DK;
        #pragma unroll
        for (int it = 0; it < 4; it++) {
            int i = tid + it * 256;
            int row = i >> 3, c8 = (i & 7) * 8;
            cp16(smem_u32(Qs + row * QLD + c8), Qg + (size_t)row * DK + c8);
        }
        cp_commit();
    }

    auto issueK = [&](int t) {
        __half* S = Ks + (t & 3) * KTS;
        int m0 = t * 64;
        #pragma unroll
        for (int it = 0; it < 2; it++) {
            int i = tid + it * 256;
            int row = i >> 3, c8 = (i & 7) * 8;
            cp16(smem_u32(S + row * KVLD + c8), Kg + (size_t)(m0 + row) * DK + c8);
        }
        cp_commit();
    };

    issueK(0); issueK(1);

    uint32_t qf[4][4];
    float* ap = out + ATTN_OFF + (size_t)ba * SEQ * SEQ
              + (size_t)(mtile * 128 + warp * 16) * SEQ;

    for (int t = 0; t < 16; t++) {
        if (t + 2 < 16) issueK(t + 2); else cp_commit();
        cp_wait<2>();
        __syncthreads();

        if (t == 0) {
            uint32_t qb = smem_u32(Qs);
            #pragma unroll
            for (int ks = 0; ks < 4; ks++) {
                uint32_t ad = qb + ((warp * 16 + (lane & 15)) * QLD
                                    + ks * 16 + (lane >> 4) * 8) * 2;
                LDSM4(qf[ks][0], qf[ks][1], qf[ks][2], qf[ks][3], ad);
            }
        }

        uint32_t kb = smem_u32(Ks + (t & 3) * KTS);

        float sacc[8][4];
        #pragma unroll
        for (int ni = 0; ni < 8; ni++)
            #pragma unroll
            for (int e = 0; e < 4; e++) sacc[ni][e] = 0.0f;

        #pragma unroll
        for (int ks = 0; ks < 4; ks++) {
            #pragma unroll
            for (int np = 0; np < 4; np++) {
                int n = np * 16 + (lane & 7) + ((lane >> 4) & 1) * 8;
                int koff = ks * 16 + ((lane >> 3) & 1) * 8;
                uint32_t b0, b1, b2, b3;
                LDSM4(b0, b1, b2, b3, kb + (n * KVLD + koff) * 2);
                mma16816(sacc[2 * np],     qf[ks], b0, b1);
                mma16816(sacc[2 * np + 1], qf[ks], b2, b3);
            }
        }

        #pragma unroll
        for (int ni = 0; ni < 8; ni++) {
            *reinterpret_cast<float2*>(ap + (size_t)g * SEQ + t * 64 + ni * 8 + 2 * tg)
                = make_float2(sacc[ni][0], sacc[ni][1]);
            *reinterpret_cast<float2*>(ap + (size_t)(g + 8) * SEQ + t * 64 + ni * 8 + 2 * tg)
                = make_float2(sacc[ni][2], sacc[ni][3]);
        }
    }
}

// ---------------------------------------------------------------------------
// k_ktv: per head KtV[64][64] = K^T V — UNCHANGED.
// ---------------------------------------------------------------------------
__global__ void __launch_bounds__(128, 4)
k_ktv() {
    __shared__ __half Kt[2][64 * 72];
    __shared__ __half Vt[2][64 * 72];

    const int tid = threadIdx.x, warp = tid >> 5, lane = tid & 31;
    const int g = lane >> 2, tg = lane & 3;
    const int ba = blockIdx.x;

    const __half* Kg = g_Kh + (size_t)ba * SEQ * DK;
    const __half* Vg = g_Vh + (size_t)ba * SEQ * DV;

    auto issue = [&](int t) {
        int st = t & 1, m0 = t * 64;
        #pragma unroll
        for (int it = 0; it < 4; it++) {
            int i = tid + it * 128;
            int row = i >> 3, c8 = (i & 7) * 8;
            cp16(smem_u32(&Kt[st][row * 72 + c8]), Kg + (size_t)(m0 + row) * DK + c8);
        }
        #pragma unroll
        for (int it = 0; it < 4; it++) {
            int i = tid + it * 128;
            int row = i >> 3, c8 = (i & 7) * 8;
            cp16(smem_u32(&Vt[st][row * 72 + c8]), Vg + (size_t)(m0 + row) * DV + c8);
        }
        cp_commit();
    };

    issue(0);
    float acc[8][4];
    #pragma unroll
    for (int ni = 0; ni < 8; ni++)
        #pragma unroll
        for (int e = 0; e < 4; e++) acc[ni][e] = 0.0f;

    const int d0 = warp * 16;
    for (int t = 0; t < 16; t++) {
        if (t + 1 < 16) issue(t + 1); else cp_commit();
        cp_wait<1>();
        __syncthreads();

        uint32_t kb = smem_u32(Kt[t & 1]);
        uint32_t vb = smem_u32(Vt[t & 1]);

        #pragma unroll
        for (int ks = 0; ks < 4; ks++) {
            int arow = ks * 16 + (lane & 7) + ((lane >> 4) & 1) * 8;
            int acol = d0 + ((lane >> 3) & 1) * 8;
            uint32_t a[4];
            LDSM4T(a[0], a[1], a[2], a[3], kb + (arow * 72 + acol) * 2);
            #pragma unroll
            for (int jp = 0; jp < 4; jp++) {
                int krow = ks * 16 + (lane & 7) + ((lane >> 3) & 1) * 8;
                int coff = jp * 16 + (lane >> 4) * 8;
                uint32_t b0, b1, b2, b3;
                LDSM4T(b0, b1, b2, b3, vb + (krow * 72 + coff) * 2);
                mma16816(acc[2 * jp],     a, b0, b1);
                mma16816(acc[2 * jp + 1], a, b2, b3);
            }
        }
        __syncthreads();
    }

    __half* dst = g_ktv + (size_t)ba * DK * DV;
    #pragma unroll
    for (int ni = 0; ni < 8; ni++) {
        *reinterpret_cast<__half2*>(dst + (d0 + g) * DV + ni * 8 + 2 * tg)
            = __floats2half2_rn(acc[ni][0], acc[ni][1]);
        *reinterpret_cast<__half2*>(dst + (d0 + g + 8) * DV + ni * 8 + 2 * tg)
            = __floats2half2_rn(acc[ni][2], acc[ni][3]);
    }
}

// ---------------------------------------------------------------------------
// k_ne: ne = Q · KtV per head — UNCHANGED.
// ---------------------------------------------------------------------------
__global__ void __launch_bounds__(128, 4)
k_ne() {
    __shared__ __half Qs[128 * 72];
    __shared__ __half Ts[64 * 72];

    const int tid = threadIdx.x, warp = tid >> 5, lane = tid & 31;
    const int g = lane >> 2, tg = lane & 3;
    const int mtile = blockIdx.x, ba = blockIdx.y;

    {
        const __half* Qg = g_Qh + ((size_t)ba * SEQ + mtile * 128) * DK;
        #pragma unroll
        for (int it = 0; it < 8; it++) {
            int i = tid + it * 128;
            int row = i >> 3, c8 = (i & 7) * 8;
            cp16(smem_u32(Qs + row * 72 + c8), Qg + (size_t)row * DK + c8);
        }
        const __half* Tg = g_ktv + (size_t)ba * DK * DV;
        #pragma unroll
        for (int it = 0; it < 4; it++) {
            int i = tid + it * 128;
            int row = i >> 3, c8 = (i & 7) * 8;
            cp16(smem_u32(Ts + row * 72 + c8), Tg + (size_t)row * DV + c8);
        }
        cp_commit();
    }
    cp_wait<0>();
    __syncthreads();

    uint32_t qb = smem_u32(Qs);
    uint32_t tb = smem_u32(Ts);

    float acc[2][8][4];
    #pragma unroll
    for (int mi = 0; mi < 2; mi++)
        #pragma unroll
        for (int ni = 0; ni < 8; ni++)
            #pragma unroll
            for (int e = 0; e < 4; e++) acc[mi][ni][e] = 0.0f;

    #pragma unroll
    for (int ks = 0; ks < 4; ks++) {
        uint32_t a[2][4];
        #pragma unroll
        for (int mi = 0; mi < 2; mi++) {
            uint32_t ad = qb + ((warp * 32 + mi * 16 + (lane & 15)) * 72
                                + ks * 16 + (lane >> 4) * 8) * 2;
            LDSM4(a[mi][0], a[mi][1], a[mi][2], a[mi][3], ad);
        }
        #pragma unroll
        for (int jp = 0; jp < 4; jp++) {
            int krow = ks * 16 + (lane & 7) + ((lane >> 3) & 1) * 8;
            int coff = jp * 16 + (lane >> 4) * 8;
            uint32_t b0, b1, b2, b3;
            LDSM4T(b0, b1, b2, b3, tb + (krow * 72 + coff) * 2);
            #pragma unroll
            for (int mi = 0; mi < 2; mi++) {
                mma16816(acc[mi][2 * jp],     a[mi], b0, b1);
                mma16816(acc[mi][2 * jp + 1], a[mi], b2, b3);
            }
        }
    }

    const int b = ba >> 4, a_ = ba & 15;
    #pragma unroll
    for (int mi = 0; mi < 2; mi++) {
        __half* ne = g_neh + ((size_t)(b * SEQ) + mtile * 128 + warp * 32 + mi * 16)
                     * (NHEAD * DV) + a_ * 64;
        #pragma unroll
        for (int jf = 0; jf < 8; jf++) {
            *reinterpret_cast<__half2*>(ne + (size_t)g * (NHEAD * DV) + jf * 8 + 2 * tg)
                = __floats2half2_rn(acc[mi][jf][0], acc[mi][jf][1]);
            *reinterpret_cast<__half2*>(ne + (size_t)(g + 8) * (NHEAD * DV) + jf * 8 + 2 * tg)
                = __floats2half2_rn(acc[mi][jf][2], acc[mi][jf][3]);
        }
    }
}

// ---------------------------------------------------------------------------
// Launch: cvt+transpose -> proj(Q,K) -> fork{ attn_s } || { proj(V) -> ktv
// -> ne -> out } -> join.  3-stage GEMM smem (61.4KB) co-resides with attn_s
// CTAs (3x55.3KB): 227.3KB <= 228KB per SM.
// ---------------------------------------------------------------------------
extern "C" void kernel_launch(void* const* d_in, const int* in_sizes, int n_in,
                              void* d_out, int out_size) {
    const float* q  = (const float*)d_in[0];
    const float* k  = (const float*)d_in[1];
    const float* v  = (const float*)d_in[2];
    const float* Wq = (const float*)d_in[3];
    const float* Wk = (const float*)d_in[4];
    const float* Wv = (const float*)d_in[5];
    const float* Wo = (const float*)d_in[6];
    float* out = (float*)d_out;
    (void)in_sizes; (void)n_in; (void)out_size;

    const int GEMM_SMEM = 3 * 2 * 128 * 40 * 2;                // 61440 B
    const int ATTN_SMEM = (128 * QLD + 4 * KTS) * 2;           // 55296 B
    cudaFuncSetAttribute(k_proj,   cudaFuncAttributeMaxDynamicSharedMemorySize, GEMM_SMEM);
    cudaFuncSetAttribute(k_out,    cudaFuncAttributeMaxDynamicSharedMemorySize, GEMM_SMEM);
    cudaFuncSetAttribute(k_attn_s, cudaFuncAttributeMaxDynamicSharedMemorySize, ATTN_SMEM);

    cudaStream_t s2;
    cudaEvent_t evF, evJ;
    cudaStreamCreateWithFlags(&s2, cudaStreamNonBlocking);
    cudaEventCreateWithFlags(&evF, cudaEventDisableTiming);
    cudaEventCreateWithFlags(&evJ, cudaEventDisableTiming);

    k_cvt<<<dim3(4096, 1, 3), 256>>>(q, k, v);
    k_transpose<<<dim3(32, 32, 4), dim3(32, 8)>>>(Wq, Wk, Wv, Wo);

    // Q and K projections only (what attn_s needs)
    k_proj<<<dim3(64, 8, 2), 128, GEMM_SMEM>>>(0);

    // Fork: attn_s on s2 || main continues with V projection + output chain
    cudaEventRecord(evF, 0);
    cudaStreamWaitEvent(s2, evF, 0);
    k_attn_s<<<dim3(8, BATCH * NHEAD), 256, ATTN_SMEM, s2>>>(out);
    cudaEventRecord(evJ, s2);

    k_proj<<<dim3(64, 8, 1), 128, GEMM_SMEM>>>(2);   // V projection
    k_ktv<<<128, 128>>>();
    k_ne<<<dim3(8, 128), 128>>>();
    k_out<<<dim3(64, 8), 128, GEMM_SMEM>>>(out);

    cudaStreamWaitEvent(0, evJ, 0);
}

// round 13
// speedup vs baseline: 1.0756x; 1.0756x over previous
#include <cuda_runtime.h>
#include <cuda_fp16.h>
#include <cstdint>

#define BATCH  8
#define SEQ    1024
#define DMODEL 1024
#define NHEAD  16
#define DK     64
#define DV     64
#define DOUT   1024
#define ATTN_OFF ((size_t)BATCH * SEQ * DOUT)

// ---------------------------------------------------------------------------
// f16 scratch
// ---------------------------------------------------------------------------
__device__ __align__(128) __half g_qh[(size_t)BATCH * SEQ * DMODEL];
__device__ __align__(128) __half g_kh[(size_t)BATCH * SEQ * DMODEL];
__device__ __align__(128) __half g_vh[(size_t)BATCH * SEQ * DMODEL];
__device__ __align__(128) __half g_Qh[(size_t)BATCH * NHEAD * SEQ * DK];  // [ba][n][d]
__device__ __align__(128) __half g_Kh[(size_t)BATCH * NHEAD * SEQ * DK];  // [ba][m][d]
__device__ __align__(128) __half g_Vh[(size_t)BATCH * NHEAD * SEQ * DV];  // [ba][m][j]
__device__ __align__(128) __half g_ktv[(size_t)BATCH * NHEAD * DK * DV];  // [ba][d][j]
__device__ __align__(128) __half g_neh[(size_t)BATCH * SEQ * NHEAD * DV]; // [b][n][a*64+j]
__device__ __align__(128) __half g_WqT[DMODEL * DMODEL];  // [out_col][in]
__device__ __align__(128) __half g_WkT[DMODEL * DMODEL];
__device__ __align__(128) __half g_WvT[DMODEL * DMODEL];
__device__ __align__(128) __half g_WoT[DMODEL * DMODEL];

// ---------------------------------------------------------------------------
// Helpers
// ---------------------------------------------------------------------------
__device__ __forceinline__ uint32_t smem_u32(const void* p) {
    return (uint32_t)__cvta_generic_to_shared(p);
}
__device__ __forceinline__ void cp16(uint32_t s, const void* g) {
    asm volatile("cp.async.cg.shared.global [%0], [%1], 16;" :: "r"(s), "l"(g));
}
__device__ __forceinline__ void cp_commit() {
    asm volatile("cp.async.commit_group;");
}
template<int N> __device__ __forceinline__ void cp_wait() {
    asm volatile("cp.async.wait_group %0;" :: "n"(N));
}
#define LDSM4(r0,r1,r2,r3,addr) \
    asm volatile("ldmatrix.sync.aligned.m8n8.x4.shared.b16 {%0,%1,%2,%3}, [%4];" \
        : "=r"(r0),"=r"(r1),"=r"(r2),"=r"(r3) : "r"(addr))
#define LDSM4T(r0,r1,r2,r3,addr) \
    asm volatile("ldmatrix.sync.aligned.m8n8.x4.trans.shared.b16 {%0,%1,%2,%3}, [%4];" \
        : "=r"(r0),"=r"(r1),"=r"(r2),"=r"(r3) : "r"(addr))
__device__ __forceinline__ void mma16816(float* c, const uint32_t* a,
                                         uint32_t b0, uint32_t b1) {
    asm volatile(
        "mma.sync.aligned.m16n8k16.row.col.f32.f16.f16.f32 "
        "{%0,%1,%2,%3}, {%4,%5,%6,%7}, {%8,%9}, {%0,%1,%2,%3};"
        : "+f"(c[0]), "+f"(c[1]), "+f"(c[2]), "+f"(c[3])
        : "r"(a[0]), "r"(a[1]), "r"(a[2]), "r"(a[3]), "r"(b0), "r"(b1));
}
__device__ __forceinline__ uint32_t packh2(float lo, float hi) {
    __half2 h = __floats2half2_rn(lo, hi);
    return *reinterpret_cast<uint32_t*>(&h);
}

// ---------------------------------------------------------------------------
// fp16 GEMM core — R9/R11-EXACT (best measured; do not modify):
// 128 threads, block 128x128, warp 64x64, BK=32, 4-stage cp.async,
// issue-before-wait, 2 CTAs/SM.
// MODE 0: f16 head-scatter -> [ba][n][d]. MODE 4: f32 row-major ldc=1024.
// ---------------------------------------------------------------------------
template<int MODE>
__device__ __forceinline__ void hgemm(
    const __half* __restrict__ Ag, int lda,
    const __half* __restrict__ Bg, int ldb,
    int nkt, void* Cb, int mtile, int ntile, __half* smem)
{
    constexpr int LD = 40;
    constexpr int TS = 128 * LD;
    constexpr int STG = 2 * TS;

    const int tid = threadIdx.x, warp = tid >> 5, lane = tid & 31;
    const int wmb = (warp >> 1) * 64, wnb = (warp & 1) * 64;
    const int g = lane >> 2, tg = lane & 3;

    float acc[4][8][4];
    #pragma unroll
    for (int mi = 0; mi < 4; mi++)
        #pragma unroll
        for (int ni = 0; ni < 8; ni++)
            #pragma unroll
            for (int e = 0; e < 4; e++) acc[mi][ni][e] = 0.0f;

    auto issue = [&](int kt) {
        __half* S = smem + (kt & 3) * STG;
        #pragma unroll
        for (int it = 0; it < 4; it++) {
            int i = tid + it * 128;
            int row = i >> 2, c8 = (i & 3) * 8;
            cp16(smem_u32(S + row * LD + c8),
                 Ag + (size_t)(mtile * 128 + row) * lda + kt * 32 + c8);
        }
        #pragma unroll
        for (int it = 0; it < 4; it++) {
            int i = tid + it * 128;
            int row = i >> 2, c8 = (i & 3) * 8;
            cp16(smem_u32(S + TS + row * LD + c8),
                 Bg + (size_t)(ntile * 128 + row) * ldb + kt * 32 + c8);
        }
        cp_commit();
    };

    issue(0); issue(1);
    for (int kt = 0; kt < nkt; kt++) {
        if (kt + 2 < nkt) issue(kt + 2); else cp_commit();
        cp_wait<2>();
        __syncthreads();

        uint32_t smA = smem_u32(smem + (kt & 3) * STG);
        uint32_t smB = smA + TS * 2;

        #pragma unroll
        for (int ks = 0; ks < 2; ks++) {
            uint32_t a[4][4];
            #pragma unroll
            for (int mi = 0; mi < 4; mi++) {
                uint32_t ad = smA + (((wmb + mi * 16 + (lane & 15)) * LD)
                                     + ks * 16 + (lane >> 4) * 8) * 2;
                LDSM4(a[mi][0], a[mi][1], a[mi][2], a[mi][3], ad);
            }
            #pragma unroll
            for (int np = 0; np < 4; np++) {
                int n = wnb + np * 16 + (lane & 7) + ((lane >> 4) & 1) * 8;
                int koff = ks * 16 + ((lane >> 3) & 1) * 8;
                uint32_t b0, b1, b2, b3;
                LDSM4(b0, b1, b2, b3, smB + (n * LD + koff) * 2);
                #pragma unroll
                for (int mi = 0; mi < 4; mi++) {
                    mma16816(acc[mi][2 * np],     a[mi], b0, b1);
                    mma16816(acc[mi][2 * np + 1], a[mi], b2, b3);
                }
            }
        }
    }

    #pragma unroll
    for (int mi = 0; mi < 4; mi++) {
        #pragma unroll
        for (int ni = 0; ni < 8; ni++) {
            #pragma unroll
            for (int h = 0; h < 2; h++) {
                int r = mtile * 128 + wmb + mi * 16 + g + h * 8;
                int c = ntile * 128 + wnb + ni * 8 + 2 * tg;
                float v0 = acc[mi][ni][h * 2], v1 = acc[mi][ni][h * 2 + 1];
                if (MODE == 0) {
                    size_t idx = (size_t)((r >> 10) * NHEAD + (c >> 6)) * ((size_t)SEQ * 64)
                               + (size_t)(r & 1023) * 64 + (c & 63);
                    *reinterpret_cast<__half2*>((__half*)Cb + idx) = __floats2half2_rn(v0, v1);
                } else {
                    *reinterpret_cast<float2*>((float*)Cb + (size_t)r * 1024 + c)
                        = make_float2(v0, v1);
                }
            }
        }
    }
}

// ---------------------------------------------------------------------------
// Small kernels
// ---------------------------------------------------------------------------
__global__ void k_cvt(const float* __restrict__ q, const float* __restrict__ k,
                      const float* __restrict__ v) {
    int z = blockIdx.z;
    const float* src = (z == 0) ? q : (z == 1) ? k : v;
    __half* dst      = (z == 0) ? g_qh : (z == 1) ? g_kh : g_vh;
    size_t i = ((size_t)blockIdx.x * 256 + threadIdx.x) * 8;
    float4 a = *reinterpret_cast<const float4*>(src + i);
    float4 b = *reinterpret_cast<const float4*>(src + i + 4);
    __half2 h0 = __floats2half2_rn(a.x, a.y), h1 = __floats2half2_rn(a.z, a.w);
    __half2 h2 = __floats2half2_rn(b.x, b.y), h3 = __floats2half2_rn(b.z, b.w);
    uint4 o;
    o.x = *reinterpret_cast<uint32_t*>(&h0); o.y = *reinterpret_cast<uint32_t*>(&h1);
    o.z = *reinterpret_cast<uint32_t*>(&h2); o.w = *reinterpret_cast<uint32_t*>(&h3);
    *reinterpret_cast<uint4*>(dst + i) = o;
}

__global__ void k_transpose(const float* __restrict__ wq, const float* __restrict__ wk,
                            const float* __restrict__ wv, const float* __restrict__ wo) {
    __shared__ float t[32][33];
    int z = blockIdx.z;
    const float* in = (z == 0) ? wq : (z == 1) ? wk : (z == 2) ? wv : wo;
    __half* outp    = (z == 0) ? g_WqT : (z == 1) ? g_WkT : (z == 2) ? g_WvT : g_WoT;
    int xi = blockIdx.x * 32 + threadIdx.x;
    int yi = blockIdx.y * 32 + threadIdx.y;
    #pragma unroll
    for (int j = 0; j < 32; j += 8)
        t[threadIdx.y + j][threadIdx.x] = in[(size_t)(yi + j) * DMODEL + xi];
    __syncthreads();
    int xo = blockIdx.y * 32 + threadIdx.x;
    int yo = blockIdx.x * 32 + threadIdx.y;
    #pragma unroll
    for (int j = 0; j < 32; j += 8)
        outp[(size_t)(yo + j) * DMODEL + xo] = __float2half_rn(t[threadIdx.x][threadIdx.y + j]);
}

// zbase: 0 -> handles z = {0(Q), 1(K)}; 2 -> handles z = 2(V)
__global__ void __launch_bounds__(128, 2)
k_proj(int zbase) {
    extern __shared__ __half hsm[];
    int z = zbase + blockIdx.z;
    if (z == 0)
        hgemm<0>(g_qh, DMODEL, g_WqT, DMODEL, 32, g_Qh, blockIdx.x, blockIdx.y, hsm);
    else if (z == 1)
        hgemm<0>(g_kh, DMODEL, g_WkT, DMODEL, 32, g_Kh, blockIdx.x, blockIdx.y, hsm);
    else
        hgemm<0>(g_vh, DMODEL, g_WvT, DMODEL, 32, g_Vh, blockIdx.x, blockIdx.y, hsm);
}

__global__ void __launch_bounds__(128, 2)
k_out(float* __restrict__ out) {
    extern __shared__ __half hsm[];
    hgemm<4>(g_neh, NHEAD * DV, g_WoT, NHEAD * DV, 32, out, blockIdx.x, blockIdx.y, hsm);
}

// ---------------------------------------------------------------------------
// k_attn_s: S = Q K^T only. 3-stage K ring (46.1KB smem -> 3 CTAs = 138KB,
// leaves 90KB so one 4-stage GEMM CTA (82KB) co-resides). Safe ordering:
// wait -> barrier -> issue (needed for 3 stages).
// ---------------------------------------------------------------------------
#define QLD 72
#define KVLD 72
#define KTS (64 * KVLD)
#define NKSTG 3

__global__ void __launch_bounds__(256, 3)
k_attn_s(float* __restrict__ out) {
    extern __shared__ __half hsm[];
    __half* Qs = hsm;                    // [128][72]
    __half* Ks = hsm + 128 * QLD;        // [3 stages][64][72]

    const int tid = threadIdx.x, warp = tid >> 5, lane = tid & 31;
    const int g = lane >> 2, tg = lane & 3;
    const int mtile = blockIdx.x, ba = blockIdx.y;

    const __half* Kg = g_Kh + (size_t)ba * SEQ * DK;

    // Stage Q (folded into first K commit group)
    {
        const __half* Qg = g_Qh + ((size_t)ba * SEQ + mtile * 128) * DK;
        #pragma unroll
        for (int it = 0; it < 4; it++) {
            int i = tid + it * 256;
            int row = i >> 3, c8 = (i & 7) * 8;
            cp16(smem_u32(Qs + row * QLD + c8), Qg + (size_t)row * DK + c8);
        }
    }

    auto issueK = [&](int t) {
        __half* S = Ks + (t % NKSTG) * KTS;
        int m0 = t * 64;
        #pragma unroll
        for (int it = 0; it < 2; it++) {
            int i = tid + it * 256;
            int row = i >> 3, c8 = (i & 7) * 8;
            cp16(smem_u32(S + row * KVLD + c8), Kg + (size_t)(m0 + row) * DK + c8);
        }
        cp_commit();
    };

    issueK(0);   // group0 = {Q, K0}
    issueK(1);

    uint32_t qf[4][4];
    float* ap = out + ATTN_OFF + (size_t)ba * SEQ * SEQ
              + (size_t)(mtile * 128 + warp * 16) * SEQ;

    for (int t = 0; t < 16; t++) {
        if (t == 15) cp_wait<0>(); else cp_wait<1>();   // stage t resident
        __syncthreads();
        if (t + 2 < 16) issueK(t + 2);   // writes slot (t-1)%3: safe post-barrier

        if (t == 0) {
            uint32_t qb = smem_u32(Qs);
            #pragma unroll
            for (int ks = 0; ks < 4; ks++) {
                uint32_t ad = qb + ((warp * 16 + (lane & 15)) * QLD
                                    + ks * 16 + (lane >> 4) * 8) * 2;
                LDSM4(qf[ks][0], qf[ks][1], qf[ks][2], qf[ks][3], ad);
            }
        }

        uint32_t kb = smem_u32(Ks + (t % NKSTG) * KTS);

        float sacc[8][4];
        #pragma unroll
        for (int ni = 0; ni < 8; ni++)
            #pragma unroll
            for (int e = 0; e < 4; e++) sacc[ni][e] = 0.0f;

        #pragma unroll
        for (int ks = 0; ks < 4; ks++) {
            #pragma unroll
            for (int np = 0; np < 4; np++) {
                int n = np * 16 + (lane & 7) + ((lane >> 4) & 1) * 8;
                int koff = ks * 16 + ((lane >> 3) & 1) * 8;
                uint32_t b0, b1, b2, b3;
                LDSM4(b0, b1, b2, b3, kb + (n * KVLD + koff) * 2);
                mma16816(sacc[2 * np],     qf[ks], b0, b1);
                mma16816(sacc[2 * np + 1], qf[ks], b2, b3);
            }
        }

        #pragma unroll
        for (int ni = 0; ni < 8; ni++) {
            *reinterpret_cast<float2*>(ap + (size_t)g * SEQ + t * 64 + ni * 8 + 2 * tg)
                = make_float2(sacc[ni][0], sacc[ni][1]);
            *reinterpret_cast<float2*>(ap + (size_t)(g + 8) * SEQ + t * 64 + ni * 8 + 2 * tg)
                = make_float2(sacc[ni][2], sacc[ni][3]);
        }
    }
}

// ---------------------------------------------------------------------------
// k_ktv: per head KtV[64][64] = K^T V — UNCHANGED.
// ---------------------------------------------------------------------------
__global__ void __launch_bounds__(128, 4)
k_ktv() {
    __shared__ __half Kt[2][64 * 72];
    __shared__ __half Vt[2][64 * 72];

    const int tid = threadIdx.x, warp = tid >> 5, lane = tid & 31;
    const int g = lane >> 2, tg = lane & 3;
    const int ba = blockIdx.x;

    const __half* Kg = g_Kh + (size_t)ba * SEQ * DK;
    const __half* Vg = g_Vh + (size_t)ba * SEQ * DV;

    auto issue = [&](int t) {
        int st = t & 1, m0 = t * 64;
        #pragma unroll
        for (int it = 0; it < 4; it++) {
            int i = tid + it * 128;
            int row = i >> 3, c8 = (i & 7) * 8;
            cp16(smem_u32(&Kt[st][row * 72 + c8]), Kg + (size_t)(m0 + row) * DK + c8);
        }
        #pragma unroll
        for (int it = 0; it < 4; it++) {
            int i = tid + it * 128;
            int row = i >> 3, c8 = (i & 7) * 8;
            cp16(smem_u32(&Vt[st][row * 72 + c8]), Vg + (size_t)(m0 + row) * DV + c8);
        }
        cp_commit();
    };

    issue(0);
    float acc[8][4];
    #pragma unroll
    for (int ni = 0; ni < 8; ni++)
        #pragma unroll
        for (int e = 0; e < 4; e++) acc[ni][e] = 0.0f;

    const int d0 = warp * 16;
    for (int t = 0; t < 16; t++) {
        if (t + 1 < 16) issue(t + 1); else cp_commit();
        cp_wait<1>();
        __syncthreads();

        uint32_t kb = smem_u32(Kt[t & 1]);
        uint32_t vb = smem_u32(Vt[t & 1]);

        #pragma unroll
        for (int ks = 0; ks < 4; ks++) {
            int arow = ks * 16 + (lane & 7) + ((lane >> 4) & 1) * 8;
            int acol = d0 + ((lane >> 3) & 1) * 8;
            uint32_t a[4];
            LDSM4T(a[0], a[1], a[2], a[3], kb + (arow * 72 + acol) * 2);
            #pragma unroll
            for (int jp = 0; jp < 4; jp++) {
                int krow = ks * 16 + (lane & 7) + ((lane >> 3) & 1) * 8;
                int coff = jp * 16 + (lane >> 4) * 8;
                uint32_t b0, b1, b2, b3;
                LDSM4T(b0, b1, b2, b3, vb + (krow * 72 + coff) * 2);
                mma16816(acc[2 * jp],     a, b0, b1);
                mma16816(acc[2 * jp + 1], a, b2, b3);
            }
        }
        __syncthreads();
    }

    __half* dst = g_ktv + (size_t)ba * DK * DV;
    #pragma unroll
    for (int ni = 0; ni < 8; ni++) {
        *reinterpret_cast<__half2*>(dst + (d0 + g) * DV + ni * 8 + 2 * tg)
            = __floats2half2_rn(acc[ni][0], acc[ni][1]);
        *reinterpret_cast<__half2*>(dst + (d0 + g + 8) * DV + ni * 8 + 2 * tg)
            = __floats2half2_rn(acc[ni][2], acc[ni][3]);
    }
}

// ---------------------------------------------------------------------------
// k_ne: ne = Q · KtV per head — UNCHANGED.
// ---------------------------------------------------------------------------
__global__ void __launch_bounds__(128, 4)
k_ne() {
    __shared__ __half Qs[128 * 72];
    __shared__ __half Ts[64 * 72];

    const int tid = threadIdx.x, warp = tid >> 5, lane = tid & 31;
    const int g = lane >> 2, tg = lane & 3;
    const int mtile = blockIdx.x, ba = blockIdx.y;

    {
        const __half* Qg = g_Qh + ((size_t)ba * SEQ + mtile * 128) * DK;
        #pragma unroll
        for (int it = 0; it < 8; it++) {
            int i = tid + it * 128;
            int row = i >> 3, c8 = (i & 7) * 8;
            cp16(smem_u32(Qs + row * 72 + c8), Qg + (size_t)row * DK + c8);
        }
        const __half* Tg = g_ktv + (size_t)ba * DK * DV;
        #pragma unroll
        for (int it = 0; it < 4; it++) {
            int i = tid + it * 128;
            int row = i >> 3, c8 = (i & 7) * 8;
            cp16(smem_u32(Ts + row * 72 + c8), Tg + (size_t)row * DV + c8);
        }
        cp_commit();
    }
    cp_wait<0>();
    __syncthreads();

    uint32_t qb = smem_u32(Qs);
    uint32_t tb = smem_u32(Ts);

    float acc[2][8][4];
    #pragma unroll
    for (int mi = 0; mi < 2; mi++)
        #pragma unroll
        for (int ni = 0; ni < 8; ni++)
            #pragma unroll
            for (int e = 0; e < 4; e++) acc[mi][ni][e] = 0.0f;

    #pragma unroll
    for (int ks = 0; ks < 4; ks++) {
        uint32_t a[2][4];
        #pragma unroll
        for (int mi = 0; mi < 2; mi++) {
            uint32_t ad = qb + ((warp * 32 + mi * 16 + (lane & 15)) * 72
                                + ks * 16 + (lane >> 4) * 8) * 2;
            LDSM4(a[mi][0], a[mi][1], a[mi][2], a[mi][3], ad);
        }
        #pragma unroll
        for (int jp = 0; jp < 4; jp++) {
            int krow = ks * 16 + (lane & 7) + ((lane >> 3) & 1) * 8;
            int coff = jp * 16 + (lane >> 4) * 8;
            uint32_t b0, b1, b2, b3;
            LDSM4T(b0, b1, b2, b3, tb + (krow * 72 + coff) * 2);
            #pragma unroll
            for (int mi = 0; mi < 2; mi++) {
                mma16816(acc[mi][2 * jp],     a[mi], b0, b1);
                mma16816(acc[mi][2 * jp + 1], a[mi], b2, b3);
            }
        }
    }

    const int b = ba >> 4, a_ = ba & 15;
    #pragma unroll
    for (int mi = 0; mi < 2; mi++) {
        __half* ne = g_neh + ((size_t)(b * SEQ) + mtile * 128 + warp * 32 + mi * 16)
                     * (NHEAD * DV) + a_ * 64;
        #pragma unroll
        for (int jf = 0; jf < 8; jf++) {
            *reinterpret_cast<__half2*>(ne + (size_t)g * (NHEAD * DV) + jf * 8 + 2 * tg)
                = __floats2half2_rn(acc[mi][jf][0], acc[mi][jf][1]);
            *reinterpret_cast<__half2*>(ne + (size_t)(g + 8) * (NHEAD * DV) + jf * 8 + 2 * tg)
                = __floats2half2_rn(acc[mi][jf][2], acc[mi][jf][3]);
        }
    }
}

// ---------------------------------------------------------------------------
// Launch: cvt+transpose -> proj(Q,K) -> fork{ attn_s } || { proj(V) -> ktv
// -> ne -> out } -> join.  attn_s 3x46.1KB = 138KB/SM leaves 90KB: one
// 4-stage GEMM CTA (82KB) co-resides -> genuine branch overlap.
// ---------------------------------------------------------------------------
extern "C" void kernel_launch(void* const* d_in, const int* in_sizes, int n_in,
                              void* d_out, int out_size) {
    const float* q  = (const float*)d_in[0];
    const float* k  = (const float*)d_in[1];
    const float* v  = (const float*)d_in[2];
    const float* Wq = (const float*)d_in[3];
    const float* Wk = (const float*)d_in[4];
    const float* Wv = (const float*)d_in[5];
    const float* Wo = (const float*)d_in[6];
    float* out = (float*)d_out;
    (void)in_sizes; (void)n_in; (void)out_size;

    const int GEMM_SMEM = 4 * 2 * 128 * 40 * 2;                    // 81920 B
    const int ATTN_SMEM = (128 * QLD + NKSTG * KTS) * 2;           // 46080 B
    cudaFuncSetAttribute(k_proj,   cudaFuncAttributeMaxDynamicSharedMemorySize, GEMM_SMEM);
    cudaFuncSetAttribute(k_out,    cudaFuncAttributeMaxDynamicSharedMemorySize, GEMM_SMEM);
    cudaFuncSetAttribute(k_attn_s, cudaFuncAttributeMaxDynamicSharedMemorySize, ATTN_SMEM);

    cudaStream_t s2;
    cudaEvent_t evF, evJ;
    cudaStreamCreateWithFlags(&s2, cudaStreamNonBlocking);
    cudaEventCreateWithFlags(&evF, cudaEventDisableTiming);
    cudaEventCreateWithFlags(&evJ, cudaEventDisableTiming);

    k_cvt<<<dim3(4096, 1, 3), 256>>>(q, k, v);
    k_transpose<<<dim3(32, 32, 4), dim3(32, 8)>>>(Wq, Wk, Wv, Wo);

    // Q and K projections only (what attn_s needs)
    k_proj<<<dim3(64, 8, 2), 128, GEMM_SMEM>>>(0);

    // Fork: attn_s on s2 || main continues with V projection + output chain
    cudaEventRecord(evF, 0);
    cudaStreamWaitEvent(s2, evF, 0);
    k_attn_s<<<dim3(8, BATCH * NHEAD), 256, ATTN_SMEM, s2>>>(out);
    cudaEventRecord(evJ, s2);

    k_proj<<<dim3(64, 8, 1), 128, GEMM_SMEM>>>(2);   // V projection
    k_ktv<<<128, 128>>>();
    k_ne<<<dim3(8, 128), 128>>>();
    k_out<<<dim3(64, 8), 128, GEMM_SMEM>>>(out);

    cudaStreamWaitEvent(0, evJ, 0);
}

// round 14
// speedup vs baseline: 1.1213x; 1.0425x over previous
#include <cuda_runtime.h>
#include <cuda_fp16.h>
#include <cstdint>

#define BATCH  8
#define SEQ    1024
#define DMODEL 1024
#define NHEAD  16
#define DK     64
#define DV     64
#define DOUT   1024
#define ATTN_OFF ((size_t)BATCH * SEQ * DOUT)

// ---------------------------------------------------------------------------
// f16 scratch
// ---------------------------------------------------------------------------
__device__ __align__(128) __half g_qh[(size_t)BATCH * SEQ * DMODEL];
__device__ __align__(128) __half g_kh[(size_t)BATCH * SEQ * DMODEL];
__device__ __align__(128) __half g_vh[(size_t)BATCH * SEQ * DMODEL];
__device__ __align__(128) __half g_Qh[(size_t)BATCH * NHEAD * SEQ * DK];  // [ba][n][d]
__device__ __align__(128) __half g_Kh[(size_t)BATCH * NHEAD * SEQ * DK];  // [ba][m][d]
__device__ __align__(128) __half g_Vh[(size_t)BATCH * NHEAD * SEQ * DV];  // [ba][m][j]
__device__ __align__(128) __half g_ktv[(size_t)BATCH * NHEAD * DK * DV];  // [ba][d][j]
__device__ __align__(128) __half g_neh[(size_t)BATCH * SEQ * NHEAD * DV]; // [b][n][a*64+j]
__device__ __align__(128) __half g_WqT[DMODEL * DMODEL];  // [out_col][in]
__device__ __align__(128) __half g_WkT[DMODEL * DMODEL];
__device__ __align__(128) __half g_WvT[DMODEL * DMODEL];
__device__ __align__(128) __half g_WoT[DMODEL * DMODEL];

// ---------------------------------------------------------------------------
// Helpers
// ---------------------------------------------------------------------------
__device__ __forceinline__ uint32_t smem_u32(const void* p) {
    return (uint32_t)__cvta_generic_to_shared(p);
}
__device__ __forceinline__ void cp16(uint32_t s, const void* g) {
    asm volatile("cp.async.cg.shared.global [%0], [%1], 16;" :: "r"(s), "l"(g));
}
__device__ __forceinline__ void cp_commit() {
    asm volatile("cp.async.commit_group;");
}
template<int N> __device__ __forceinline__ void cp_wait() {
    asm volatile("cp.async.wait_group %0;" :: "n"(N));
}
#define LDSM4(r0,r1,r2,r3,addr) \
    asm volatile("ldmatrix.sync.aligned.m8n8.x4.shared.b16 {%0,%1,%2,%3}, [%4];" \
        : "=r"(r0),"=r"(r1),"=r"(r2),"=r"(r3) : "r"(addr))
#define LDSM4T(r0,r1,r2,r3,addr) \
    asm volatile("ldmatrix.sync.aligned.m8n8.x4.trans.shared.b16 {%0,%1,%2,%3}, [%4];" \
        : "=r"(r0),"=r"(r1),"=r"(r2),"=r"(r3) : "r"(addr))
__device__ __forceinline__ void mma16816(float* c, const uint32_t* a,
                                         uint32_t b0, uint32_t b1) {
    asm volatile(
        "mma.sync.aligned.m16n8k16.row.col.f32.f16.f16.f32 "
        "{%0,%1,%2,%3}, {%4,%5,%6,%7}, {%8,%9}, {%0,%1,%2,%3};"
        : "+f"(c[0]), "+f"(c[1]), "+f"(c[2]), "+f"(c[3])
        : "r"(a[0]), "r"(a[1]), "r"(a[2]), "r"(a[3]), "r"(b0), "r"(b1));
}
__device__ __forceinline__ uint32_t packh2(float lo, float hi) {
    __half2 h = __floats2half2_rn(lo, hi);
    return *reinterpret_cast<uint32_t*>(&h);
}

// ---------------------------------------------------------------------------
// fp16 GEMM core — R9/R11-EXACT (best measured; do not modify):
// 128 threads, block 128x128, warp 64x64, BK=32, 4-stage cp.async,
// issue-before-wait, 2 CTAs/SM.
// MODE 0: f16 head-scatter -> [ba][n][d]. MODE 4: f32 row-major ldc=1024.
// ---------------------------------------------------------------------------
template<int MODE>
__device__ __forceinline__ void hgemm(
    const __half* __restrict__ Ag, int lda,
    const __half* __restrict__ Bg, int ldb,
    int nkt, void* Cb, int mtile, int ntile, __half* smem)
{
    constexpr int LD = 40;
    constexpr int TS = 128 * LD;
    constexpr int STG = 2 * TS;

    const int tid = threadIdx.x, warp = tid >> 5, lane = tid & 31;
    const int wmb = (warp >> 1) * 64, wnb = (warp & 1) * 64;
    const int g = lane >> 2, tg = lane & 3;

    float acc[4][8][4];
    #pragma unroll
    for (int mi = 0; mi < 4; mi++)
        #pragma unroll
        for (int ni = 0; ni < 8; ni++)
            #pragma unroll
            for (int e = 0; e < 4; e++) acc[mi][ni][e] = 0.0f;

    auto issue = [&](int kt) {
        __half* S = smem + (kt & 3) * STG;
        #pragma unroll
        for (int it = 0; it < 4; it++) {
            int i = tid + it * 128;
            int row = i >> 2, c8 = (i & 3) * 8;
            cp16(smem_u32(S + row * LD + c8),
                 Ag + (size_t)(mtile * 128 + row) * lda + kt * 32 + c8);
        }
        #pragma unroll
        for (int it = 0; it < 4; it++) {
            int i = tid + it * 128;
            int row = i >> 2, c8 = (i & 3) * 8;
            cp16(smem_u32(S + TS + row * LD + c8),
                 Bg + (size_t)(ntile * 128 + row) * ldb + kt * 32 + c8);
        }
        cp_commit();
    };

    issue(0); issue(1);
    for (int kt = 0; kt < nkt; kt++) {
        if (kt + 2 < nkt) issue(kt + 2); else cp_commit();
        cp_wait<2>();
        __syncthreads();

        uint32_t smA = smem_u32(smem + (kt & 3) * STG);
        uint32_t smB = smA + TS * 2;

        #pragma unroll
        for (int ks = 0; ks < 2; ks++) {
            uint32_t a[4][4];
            #pragma unroll
            for (int mi = 0; mi < 4; mi++) {
                uint32_t ad = smA + (((wmb + mi * 16 + (lane & 15)) * LD)
                                     + ks * 16 + (lane >> 4) * 8) * 2;
                LDSM4(a[mi][0], a[mi][1], a[mi][2], a[mi][3], ad);
            }
            #pragma unroll
            for (int np = 0; np < 4; np++) {
                int n = wnb + np * 16 + (lane & 7) + ((lane >> 4) & 1) * 8;
                int koff = ks * 16 + ((lane >> 3) & 1) * 8;
                uint32_t b0, b1, b2, b3;
                LDSM4(b0, b1, b2, b3, smB + (n * LD + koff) * 2);
                #pragma unroll
                for (int mi = 0; mi < 4; mi++) {
                    mma16816(acc[mi][2 * np],     a[mi], b0, b1);
                    mma16816(acc[mi][2 * np + 1], a[mi], b2, b3);
                }
            }
        }
    }

    #pragma unroll
    for (int mi = 0; mi < 4; mi++) {
        #pragma unroll
        for (int ni = 0; ni < 8; ni++) {
            #pragma unroll
            for (int h = 0; h < 2; h++) {
                int r = mtile * 128 + wmb + mi * 16 + g + h * 8;
                int c = ntile * 128 + wnb + ni * 8 + 2 * tg;
                float v0 = acc[mi][ni][h * 2], v1 = acc[mi][ni][h * 2 + 1];
                if (MODE == 0) {
                    size_t idx = (size_t)((r >> 10) * NHEAD + (c >> 6)) * ((size_t)SEQ * 64)
                               + (size_t)(r & 1023) * 64 + (c & 63);
                    *reinterpret_cast<__half2*>((__half*)Cb + idx) = __floats2half2_rn(v0, v1);
                } else {
                    *reinterpret_cast<float2*>((float*)Cb + (size_t)r * 1024 + c)
                        = make_float2(v0, v1);
                }
            }
        }
    }
}

// ---------------------------------------------------------------------------
// Small kernels
// ---------------------------------------------------------------------------
__global__ void k_cvt(const float* __restrict__ q, const float* __restrict__ k,
                      const float* __restrict__ v) {
    int z = blockIdx.z;
    const float* src = (z == 0) ? q : (z == 1) ? k : v;
    __half* dst      = (z == 0) ? g_qh : (z == 1) ? g_kh : g_vh;
    size_t i = ((size_t)blockIdx.x * 256 + threadIdx.x) * 8;
    float4 a = *reinterpret_cast<const float4*>(src + i);
    float4 b = *reinterpret_cast<const float4*>(src + i + 4);
    __half2 h0 = __floats2half2_rn(a.x, a.y), h1 = __floats2half2_rn(a.z, a.w);
    __half2 h2 = __floats2half2_rn(b.x, b.y), h3 = __floats2half2_rn(b.z, b.w);
    uint4 o;
    o.x = *reinterpret_cast<uint32_t*>(&h0); o.y = *reinterpret_cast<uint32_t*>(&h1);
    o.z = *reinterpret_cast<uint32_t*>(&h2); o.w = *reinterpret_cast<uint32_t*>(&h3);
    *reinterpret_cast<uint4*>(dst + i) = o;
}

__global__ void k_transpose(const float* __restrict__ wq, const float* __restrict__ wk,
                            const float* __restrict__ wv, const float* __restrict__ wo) {
    __shared__ float t[32][33];
    int z = blockIdx.z;
    const float* in = (z == 0) ? wq : (z == 1) ? wk : (z == 2) ? wv : wo;
    __half* outp    = (z == 0) ? g_WqT : (z == 1) ? g_WkT : (z == 2) ? g_WvT : g_WoT;
    int xi = blockIdx.x * 32 + threadIdx.x;
    int yi = blockIdx.y * 32 + threadIdx.y;
    #pragma unroll
    for (int j = 0; j < 32; j += 8)
        t[threadIdx.y + j][threadIdx.x] = in[(size_t)(yi + j) * DMODEL + xi];
    __syncthreads();
    int xo = blockIdx.y * 32 + threadIdx.x;
    int yo = blockIdx.x * 32 + threadIdx.y;
    #pragma unroll
    for (int j = 0; j < 32; j += 8)
        outp[(size_t)(yo + j) * DMODEL + xo] = __float2half_rn(t[threadIdx.x][threadIdx.y + j]);
}

__global__ void __launch_bounds__(128, 2)
k_proj() {
    extern __shared__ __half hsm[];
    int z = blockIdx.z;
    if (z == 0)
        hgemm<0>(g_qh, DMODEL, g_WqT, DMODEL, 32, g_Qh, blockIdx.x, blockIdx.y, hsm);
    else if (z == 1)
        hgemm<0>(g_kh, DMODEL, g_WkT, DMODEL, 32, g_Kh, blockIdx.x, blockIdx.y, hsm);
    else
        hgemm<0>(g_vh, DMODEL, g_WvT, DMODEL, 32, g_Vh, blockIdx.x, blockIdx.y, hsm);
}

__global__ void __launch_bounds__(128, 2)
k_out(float* __restrict__ out) {
    extern __shared__ __half hsm[];
    hgemm<4>(g_neh, NHEAD * DV, g_WoT, NHEAD * DV, 32, out, blockIdx.x, blockIdx.y, hsm);
}

// ---------------------------------------------------------------------------
// k_attn_s: S = Q K^T only. 3-stage K ring (46.1KB smem, measured 110.2us).
// 3 CTAs/SM = 138KB leaves 90KB -> one 82KB k_out CTA co-resides.
// ---------------------------------------------------------------------------
#define QLD 72
#define KVLD 72
#define KTS (64 * KVLD)
#define NKSTG 3

__global__ void __launch_bounds__(256, 3)
k_attn_s(float* __restrict__ out) {
    extern __shared__ __half hsm[];
    __half* Qs = hsm;                    // [128][72]
    __half* Ks = hsm + 128 * QLD;        // [3 stages][64][72]

    const int tid = threadIdx.x, warp = tid >> 5, lane = tid & 31;
    const int g = lane >> 2, tg = lane & 3;
    const int mtile = blockIdx.x, ba = blockIdx.y;

    const __half* Kg = g_Kh + (size_t)ba * SEQ * DK;

    // Stage Q (folded into first K commit group)
    {
        const __half* Qg = g_Qh + ((size_t)ba * SEQ + mtile * 128) * DK;
        #pragma unroll
        for (int it = 0; it < 4; it++) {
            int i = tid + it * 256;
            int row = i >> 3, c8 = (i & 7) * 8;
            cp16(smem_u32(Qs + row * QLD + c8), Qg + (size_t)row * DK + c8);
        }
    }

    auto issueK = [&](int t) {
        __half* S = Ks + (t % NKSTG) * KTS;
        int m0 = t * 64;
        #pragma unroll
        for (int it = 0; it < 2; it++) {
            int i = tid + it * 256;
            int row = i >> 3, c8 = (i & 7) * 8;
            cp16(smem_u32(S + row * KVLD + c8), Kg + (size_t)(m0 + row) * DK + c8);
        }
        cp_commit();
    };

    issueK(0);   // group0 = {Q, K0}
    issueK(1);

    uint32_t qf[4][4];
    float* ap = out + ATTN_OFF + (size_t)ba * SEQ * SEQ
              + (size_t)(mtile * 128 + warp * 16) * SEQ;

    for (int t = 0; t < 16; t++) {
        if (t == 15) cp_wait<0>(); else cp_wait<1>();   // stage t resident
        __syncthreads();
        if (t + 2 < 16) issueK(t + 2);   // writes slot (t-1)%3: safe post-barrier

        if (t == 0) {
            uint32_t qb = smem_u32(Qs);
            #pragma unroll
            for (int ks = 0; ks < 4; ks++) {
                uint32_t ad = qb + ((warp * 16 + (lane & 15)) * QLD
                                    + ks * 16 + (lane >> 4) * 8) * 2;
                LDSM4(qf[ks][0], qf[ks][1], qf[ks][2], qf[ks][3], ad);
            }
        }

        uint32_t kb = smem_u32(Ks + (t % NKSTG) * KTS);

        float sacc[8][4];
        #pragma unroll
        for (int ni = 0; ni < 8; ni++)
            #pragma unroll
            for (int e = 0; e < 4; e++) sacc[ni][e] = 0.0f;

        #pragma unroll
        for (int ks = 0; ks < 4; ks++) {
            #pragma unroll
            for (int np = 0; np < 4; np++) {
                int n = np * 16 + (lane & 7) + ((lane >> 4) & 1) * 8;
                int koff = ks * 16 + ((lane >> 3) & 1) * 8;
                uint32_t b0, b1, b2, b3;
                LDSM4(b0, b1, b2, b3, kb + (n * KVLD + koff) * 2);
                mma16816(sacc[2 * np],     qf[ks], b0, b1);
                mma16816(sacc[2 * np + 1], qf[ks], b2, b3);
            }
        }

        #pragma unroll
        for (int ni = 0; ni < 8; ni++) {
            *reinterpret_cast<float2*>(ap + (size_t)g * SEQ + t * 64 + ni * 8 + 2 * tg)
                = make_float2(sacc[ni][0], sacc[ni][1]);
            *reinterpret_cast<float2*>(ap + (size_t)(g + 8) * SEQ + t * 64 + ni * 8 + 2 * tg)
                = make_float2(sacc[ni][2], sacc[ni][3]);
        }
    }
}

// ---------------------------------------------------------------------------
// k_ktv: per head KtV[64][64] = K^T V — UNCHANGED.
// ---------------------------------------------------------------------------
__global__ void __launch_bounds__(128, 4)
k_ktv() {
    __shared__ __half Kt[2][64 * 72];
    __shared__ __half Vt[2][64 * 72];

    const int tid = threadIdx.x, warp = tid >> 5, lane = tid & 31;
    const int g = lane >> 2, tg = lane & 3;
    const int ba = blockIdx.x;

    const __half* Kg = g_Kh + (size_t)ba * SEQ * DK;
    const __half* Vg = g_Vh + (size_t)ba * SEQ * DV;

    auto issue = [&](int t) {
        int st = t & 1, m0 = t * 64;
        #pragma unroll
        for (int it = 0; it < 4; it++) {
            int i = tid + it * 128;
            int row = i >> 3, c8 = (i & 7) * 8;
            cp16(smem_u32(&Kt[st][row * 72 + c8]), Kg + (size_t)(m0 + row) * DK + c8);
        }
        #pragma unroll
        for (int it = 0; it < 4; it++) {
            int i = tid + it * 128;
            int row = i >> 3, c8 = (i & 7) * 8;
            cp16(smem_u32(&Vt[st][row * 72 + c8]), Vg + (size_t)(m0 + row) * DV + c8);
        }
        cp_commit();
    };

    issue(0);
    float acc[8][4];
    #pragma unroll
    for (int ni = 0; ni < 8; ni++)
        #pragma unroll
        for (int e = 0; e < 4; e++) acc[ni][e] = 0.0f;

    const int d0 = warp * 16;
    for (int t = 0; t < 16; t++) {
        if (t + 1 < 16) issue(t + 1); else cp_commit();
        cp_wait<1>();
        __syncthreads();

        uint32_t kb = smem_u32(Kt[t & 1]);
        uint32_t vb = smem_u32(Vt[t & 1]);

        #pragma unroll
        for (int ks = 0; ks < 4; ks++) {
            int arow = ks * 16 + (lane & 7) + ((lane >> 4) & 1) * 8;
            int acol = d0 + ((lane >> 3) & 1) * 8;
            uint32_t a[4];
            LDSM4T(a[0], a[1], a[2], a[3], kb + (arow * 72 + acol) * 2);
            #pragma unroll
            for (int jp = 0; jp < 4; jp++) {
                int krow = ks * 16 + (lane & 7) + ((lane >> 3) & 1) * 8;
                int coff = jp * 16 + (lane >> 4) * 8;
                uint32_t b0, b1, b2, b3;
                LDSM4T(b0, b1, b2, b3, vb + (krow * 72 + coff) * 2);
                mma16816(acc[2 * jp],     a, b0, b1);
                mma16816(acc[2 * jp + 1], a, b2, b3);
            }
        }
        __syncthreads();
    }

    __half* dst = g_ktv + (size_t)ba * DK * DV;
    #pragma unroll
    for (int ni = 0; ni < 8; ni++) {
        *reinterpret_cast<__half2*>(dst + (d0 + g) * DV + ni * 8 + 2 * tg)
            = __floats2half2_rn(acc[ni][0], acc[ni][1]);
        *reinterpret_cast<__half2*>(dst + (d0 + g + 8) * DV + ni * 8 + 2 * tg)
            = __floats2half2_rn(acc[ni][2], acc[ni][3]);
    }
}

// ---------------------------------------------------------------------------
// k_ne: ne = Q · KtV per head — UNCHANGED.
// ---------------------------------------------------------------------------
__global__ void __launch_bounds__(128, 4)
k_ne() {
    __shared__ __half Qs[128 * 72];
    __shared__ __half Ts[64 * 72];

    const int tid = threadIdx.x, warp = tid >> 5, lane = tid & 31;
    const int g = lane >> 2, tg = lane & 3;
    const int mtile = blockIdx.x, ba = blockIdx.y;

    {
        const __half* Qg = g_Qh + ((size_t)ba * SEQ + mtile * 128) * DK;
        #pragma unroll
        for (int it = 0; it < 8; it++) {
            int i = tid + it * 128;
            int row = i >> 3, c8 = (i & 7) * 8;
            cp16(smem_u32(Qs + row * 72 + c8), Qg + (size_t)row * DK + c8);
        }
        const __half* Tg = g_ktv + (size_t)ba * DK * DV;
        #pragma unroll
        for (int it = 0; it < 4; it++) {
            int i = tid + it * 128;
            int row = i >> 3, c8 = (i & 7) * 8;
            cp16(smem_u32(Ts + row * 72 + c8), Tg + (size_t)row * DV + c8);
        }
        cp_commit();
    }
    cp_wait<0>();
    __syncthreads();

    uint32_t qb = smem_u32(Qs);
    uint32_t tb = smem_u32(Ts);

    float acc[2][8][4];
    #pragma unroll
    for (int mi = 0; mi < 2; mi++)
        #pragma unroll
        for (int ni = 0; ni < 8; ni++)
            #pragma unroll
            for (int e = 0; e < 4; e++) acc[mi][ni][e] = 0.0f;

    #pragma unroll
    for (int ks = 0; ks < 4; ks++) {
        uint32_t a[2][4];
        #pragma unroll
        for (int mi = 0; mi < 2; mi++) {
            uint32_t ad = qb + ((warp * 32 + mi * 16 + (lane & 15)) * 72
                                + ks * 16 + (lane >> 4) * 8) * 2;
            LDSM4(a[mi][0], a[mi][1], a[mi][2], a[mi][3], ad);
        }
        #pragma unroll
        for (int jp = 0; jp < 4; jp++) {
            int krow = ks * 16 + (lane & 7) + ((lane >> 3) & 1) * 8;
            int coff = jp * 16 + (lane >> 4) * 8;
            uint32_t b0, b1, b2, b3;
            LDSM4T(b0, b1, b2, b3, tb + (krow * 72 + coff) * 2);
            #pragma unroll
            for (int mi = 0; mi < 2; mi++) {
                mma16816(acc[mi][2 * jp],     a[mi], b0, b1);
                mma16816(acc[mi][2 * jp + 1], a[mi], b2, b3);
            }
        }
    }

    const int b = ba >> 4, a_ = ba & 15;
    #pragma unroll
    for (int mi = 0; mi < 2; mi++) {
        __half* ne = g_neh + ((size_t)(b * SEQ) + mtile * 128 + warp * 32 + mi * 16)
                     * (NHEAD * DV) + a_ * 64;
        #pragma unroll
        for (int jf = 0; jf < 8; jf++) {
            *reinterpret_cast<__half2*>(ne + (size_t)g * (NHEAD * DV) + jf * 8 + 2 * tg)
                = __floats2half2_rn(acc[mi][jf][0], acc[mi][jf][1]);
            *reinterpret_cast<__half2*>(ne + (size_t)(g + 8) * (NHEAD * DV) + jf * 8 + 2 * tg)
                = __floats2half2_rn(acc[mi][jf][2], acc[mi][jf][3]);
        }
    }
}

// ---------------------------------------------------------------------------
// Launch (R11 topology + 3-stage attn_s): cvt -> transpose -> proj(all 3,
// one launch) -> fork{ attn_s (s2) } || { ktv -> ne -> k_out } -> join.
// attn_s 3x46.1KB=138KB + k_out 82KB = 220KB <= 228KB: genuine co-residency.
// ---------------------------------------------------------------------------
extern "C" void kernel_launch(void* const* d_in, const int* in_sizes, int n_in,
                              void* d_out, int out_size) {
    const float* q  = (const float*)d_in[0];
    const float* k  = (const float*)d_in[1];
    const float* v  = (const float*)d_in[2];
    const float* Wq = (const float*)d_in[3];
    const float* Wk = (const float*)d_in[4];
    const float* Wv = (const float*)d_in[5];
    const float* Wo = (const float*)d_in[6];
    float* out = (float*)d_out;
    (void)in_sizes; (void)n_in; (void)out_size;

    const int GEMM_SMEM = 4 * 2 * 128 * 40 * 2;                    // 81920 B
    const int ATTN_SMEM = (128 * QLD + NKSTG * KTS) * 2;           // 46080 B
    cudaFuncSetAttribute(k_proj,   cudaFuncAttributeMaxDynamicSharedMemorySize, GEMM_SMEM);
    cudaFuncSetAttribute(k_out,    cudaFuncAttributeMaxDynamicSharedMemorySize, GEMM_SMEM);
    cudaFuncSetAttribute(k_attn_s, cudaFuncAttributeMaxDynamicSharedMemorySize, ATTN_SMEM);

    cudaStream_t s2;
    cudaEvent_t evF, evJ;
    cudaStreamCreateWithFlags(&s2, cudaStreamNonBlocking);
    cudaEventCreateWithFlags(&evF, cudaEventDisableTiming);
    cudaEventCreateWithFlags(&evJ, cudaEventDisableTiming);

    k_cvt<<<dim3(4096, 1, 3), 256>>>(q, k, v);
    k_transpose<<<dim3(32, 32, 4), dim3(32, 8)>>>(Wq, Wk, Wv, Wo);
    k_proj<<<dim3(64, 8, 3), 128, GEMM_SMEM>>>();   // Q, K, V in one launch

    // Fork: attn_s on s2 || main: ktv -> ne -> k_out
    cudaEventRecord(evF, 0);
    cudaStreamWaitEvent(s2, evF, 0);
    k_attn_s<<<dim3(8, BATCH * NHEAD), 256, ATTN_SMEM, s2>>>(out);
    cudaEventRecord(evJ, s2);

    k_ktv<<<128, 128>>>();
    k_ne<<<dim3(8, 128), 128>>>();
    k_out<<<dim3(64, 8), 128, GEMM_SMEM>>>(out);

    cudaStreamWaitEvent(0, evJ, 0);
}